// round 9
// baseline (speedup 1.0000x reference)
#include <cuda_runtime.h>
#include <cuda_fp16.h>

#define VDIM 128
#define NB   8
#define SLAB 16384
#define VOL  2097152

typedef unsigned long long ull;

// Scratch spectrum stored as half2: 8 * 128^3 * 4 B = 67 MB (static alloc allowed).
__device__ __half2 g_Z[(size_t)NB * VOL];

__device__ __forceinline__ int brev7(int x) { return (int)(__brev((unsigned)x) >> 25); }
__device__ __forceinline__ int bneg7(int j) {
    int k = brev7(j); k = (VDIM - k) & 127; return brev7(k);
}

__device__ __forceinline__ __half2 pack_h2(float2 v) { return __floats2half2_rn(v.x, v.y); }
__device__ __forceinline__ float2 unpack_h2(__half2 h) { return __half22float2(h); }

// ---- f32x2 packed helpers (carrier = ull) ----
__device__ __forceinline__ ull pk(float lo, float hi) {
    ull u; asm("mov.b64 %0,{%1,%2};" : "=l"(u) : "f"(lo), "f"(hi)); return u;
}
__device__ __forceinline__ void upk(float& lo, float& hi, ull u) {
    asm("mov.b64 {%0,%1},%2;" : "=f"(lo), "=f"(hi) : "l"(u));
}
__device__ __forceinline__ ull vadd(ull a, ull b) {
    ull d; asm("add.rn.f32x2 %0,%1,%2;" : "=l"(d) : "l"(a), "l"(b)); return d;
}
__device__ __forceinline__ ull vmul(ull a, ull b) {
    ull d; asm("mul.rn.f32x2 %0,%1,%2;" : "=l"(d) : "l"(a), "l"(b)); return d;
}
__device__ __forceinline__ ull vfma(ull a, ull b, ull c) {
    ull d; asm("fma.rn.f32x2 %0,%1,%2,%3;" : "=l"(d) : "l"(a), "l"(b), "l"(c)); return d;
}

// vector butterflies: both lanes run identical bf with identical twiddle.
// w = (wx,wy); tables hold WX={wx,wx}, WY={wy,wy}, NY={-wy,-wy}.
__device__ __forceinline__ void vbf_fwd(ull& are, ull& aim, ull& bre, ull& bim,
                                        ull wx, ull wy, ull ny, ull NEG1) {
    ull sre = vadd(are, bre), sim = vadd(aim, bim);
    ull dre = vfma(bre, NEG1, are), dim = vfma(bim, NEG1, aim);
    bre = vfma(dim, ny, vmul(dre, wx));
    bim = vfma(dim, wx, vmul(dre, wy));
    are = sre; aim = sim;
}
__device__ __forceinline__ void vbf_inv(ull& are, ull& aim, ull& bre, ull& bim,
                                        ull wx, ull wy, ull ny, ull NEG1) {
    ull tre = vfma(bim, wy, vmul(bre, wx));   // t = b * conj(w)
    ull tim = vfma(bre, ny, vmul(bim, wx));
    ull nbre = vfma(tre, NEG1, are), nbim = vfma(tim, NEG1, aim);
    are = vadd(are, tre); aim = vadd(aim, tim);
    bre = nbre; bim = nbim;
}
__device__ __forceinline__ void vbf_triv(ull& are, ull& aim, ull& bre, ull& bim, ull NEG1) {
    ull dre = vfma(bre, NEG1, are), dim = vfma(bim, NEG1, aim);
    are = vadd(are, bre); aim = vadd(aim, bim);
    bre = dre; bim = dim;
}

// Vector twiddle tables: [0..63]=tw, [64..79]=tw4, [80..87]=tw8 (duplicated pairs).
__device__ __forceinline__ void init_vtw(ull* WX, ull* WY, ull* NY) {
    for (int i = threadIdx.x; i < 64; i += blockDim.x) {
        float sn, cs; sincospif(i * (1.0f / 64.0f), &sn, &cs);   // w = (cs, -sn)
        WX[i] = pk(cs, cs); WY[i] = pk(-sn, -sn); NY[i] = pk(sn, sn);
        if (!(i & 3)) { int k = 64 + (i >> 2); WX[k] = pk(cs, cs); WY[k] = pk(-sn, -sn); NY[k] = pk(sn, sn); }
        if (!(i & 7)) { int k = 80 + (i >> 3); WX[k] = pk(cs, cs); WY[k] = pk(-sn, -sn); NY[k] = pk(sn, sn); }
    }
}

// Vector FFTs over line-pairs. Same index algebra as the scalar (verified) code.
__device__ __forceinline__ void fftA_fwd_v(ull Rre[16], ull Rim[16], int t,
                                           const ull* WX, const ull* WY, const ull* NY, ull NEG1) {
    #pragma unroll
    for (int j = 0; j < 8; ++j) { int i = t + 8 * j;
        vbf_fwd(Rre[j], Rim[j], Rre[j + 8], Rim[j + 8], WX[i], WY[i], NY[i], NEG1); }
    #pragma unroll
    for (int g = 0; g < 8; ++g) { int j = ((g & ~3) << 1) | (g & 3); int i = 2 * (t + 8 * (j & 3));
        vbf_fwd(Rre[j], Rim[j], Rre[j + 4], Rim[j + 4], WX[i], WY[i], NY[i], NEG1); }
    #pragma unroll
    for (int g = 0; g < 8; ++g) { int j = ((g & ~1) << 1) | (g & 1); int i = 64 + t + 8 * (j & 1);
        vbf_fwd(Rre[j], Rim[j], Rre[j + 2], Rim[j + 2], WX[i], WY[i], NY[i], NEG1); }
    #pragma unroll
    for (int g = 0; g < 8; ++g) { int j = 2 * g; int i = 80 + t;
        vbf_fwd(Rre[j], Rim[j], Rre[j + 1], Rim[j + 1], WX[i], WY[i], NY[i], NEG1); }
}
__device__ __forceinline__ void fftA_inv_v(ull Rre[16], ull Rim[16], int t,
                                           const ull* WX, const ull* WY, const ull* NY, ull NEG1) {
    #pragma unroll
    for (int g = 0; g < 8; ++g) { int j = 2 * g; int i = 80 + t;
        vbf_inv(Rre[j], Rim[j], Rre[j + 1], Rim[j + 1], WX[i], WY[i], NY[i], NEG1); }
    #pragma unroll
    for (int g = 0; g < 8; ++g) { int j = ((g & ~1) << 1) | (g & 1); int i = 64 + t + 8 * (j & 1);
        vbf_inv(Rre[j], Rim[j], Rre[j + 2], Rim[j + 2], WX[i], WY[i], NY[i], NEG1); }
    #pragma unroll
    for (int g = 0; g < 8; ++g) { int j = ((g & ~3) << 1) | (g & 3); int i = 2 * (t + 8 * (j & 3));
        vbf_inv(Rre[j], Rim[j], Rre[j + 4], Rim[j + 4], WX[i], WY[i], NY[i], NEG1); }
    #pragma unroll
    for (int j = 0; j < 8; ++j) { int i = t + 8 * j;
        vbf_inv(Rre[j], Rim[j], Rre[j + 8], Rim[j + 8], WX[i], WY[i], NY[i], NEG1); }
}
__device__ __forceinline__ void fftB_fwd_v(ull Rre[16], ull Rim[16],
                                           const ull* WX, const ull* WY, const ull* NY, ull NEG1) {
    #pragma unroll
    for (int g = 0; g < 8; ++g) { int m = ((g & ~3) << 1) | (g & 3); int i = (m & 3) << 4;
        vbf_fwd(Rre[m], Rim[m], Rre[m + 4], Rim[m + 4], WX[i], WY[i], NY[i], NEG1); }
    #pragma unroll
    for (int g = 0; g < 8; ++g) { int m = ((g & ~1) << 1) | (g & 1); int i = (m & 1) << 5;
        vbf_fwd(Rre[m], Rim[m], Rre[m + 2], Rim[m + 2], WX[i], WY[i], NY[i], NEG1); }
    #pragma unroll
    for (int g = 0; g < 8; ++g) { int m = 2 * g;
        vbf_triv(Rre[m], Rim[m], Rre[m + 1], Rim[m + 1], NEG1); }
}
__device__ __forceinline__ void fftB_inv_v(ull Rre[16], ull Rim[16],
                                           const ull* WX, const ull* WY, const ull* NY, ull NEG1) {
    #pragma unroll
    for (int g = 0; g < 8; ++g) { int m = 2 * g;
        vbf_triv(Rre[m], Rim[m], Rre[m + 1], Rim[m + 1], NEG1); }
    #pragma unroll
    for (int g = 0; g < 8; ++g) { int m = ((g & ~1) << 1) | (g & 1); int i = (m & 1) << 5;
        vbf_inv(Rre[m], Rim[m], Rre[m + 2], Rim[m + 2], WX[i], WY[i], NY[i], NEG1); }
    #pragma unroll
    for (int g = 0; g < 8; ++g) { int m = ((g & ~3) << 1) | (g & 3); int i = (m & 3) << 4;
        vbf_inv(Rre[m], Rim[m], Rre[m + 4], Rim[m + 4], WX[i], WY[i], NY[i], NEG1); }
}

// ---- scalar machinery (passB, unchanged from passing R8 kernel) ----
__device__ __forceinline__ int sidxAC(int y, int x) {
    int c = x ^ ((x >> 4) & 7) ^ ((x & 1) << 3)
              ^ (y & 7) ^ ((y >> 4) & 7) ^ ((y & 1) << 3);
    return (y << 7) + c;
}
__device__ __forceinline__ int sidxB(int l, int z) {
    int c = z ^ ((z >> 4) & 7) ^ (l & 15);
    return (l << 7) + c;
}
__device__ __forceinline__ float2 cmul(float2 a, float2 w) {
    return make_float2(a.x * w.x - a.y * w.y, a.x * w.y + a.y * w.x);
}
__device__ __forceinline__ float2 cmulc(float2 a, float2 w) {
    return make_float2(a.x * w.x + a.y * w.y, a.y * w.x - a.x * w.y);
}
__device__ __forceinline__ void bf_fwd(float2& ra, float2& rb, float2 w) {
    float2 a = ra, b = rb;
    ra = make_float2(a.x + b.x, a.y + b.y);
    rb = cmul(make_float2(a.x - b.x, a.y - b.y), w);
}
__device__ __forceinline__ void bf_inv(float2& ra, float2& rb, float2 w) {
    float2 a = ra, t = cmulc(rb, w);
    ra = make_float2(a.x + t.x, a.y + t.y);
    rb = make_float2(a.x - t.x, a.y - t.y);
}
__device__ __forceinline__ void fftA_fwd(float2 r[16], int t, const float2* tw,
                                         const float2* tw4, const float2* tw8) {
    #pragma unroll
    for (int j = 0; j < 8; ++j) bf_fwd(r[j], r[j + 8], tw[t + 8 * j]);
    #pragma unroll
    for (int g = 0; g < 8; ++g) { int j = ((g & ~3) << 1) | (g & 3); bf_fwd(r[j], r[j + 4], tw[2 * (t + 8 * (j & 3))]); }
    #pragma unroll
    for (int g = 0; g < 8; ++g) { int j = ((g & ~1) << 1) | (g & 1); bf_fwd(r[j], r[j + 2], tw4[t + 8 * (j & 1)]); }
    #pragma unroll
    for (int g = 0; g < 8; ++g) { int j = 2 * g; bf_fwd(r[j], r[j + 1], tw8[t]); }
}
__device__ __forceinline__ void fftA_inv(float2 r[16], int t, const float2* tw,
                                         const float2* tw4, const float2* tw8) {
    #pragma unroll
    for (int g = 0; g < 8; ++g) { int j = 2 * g; bf_inv(r[j], r[j + 1], tw8[t]); }
    #pragma unroll
    for (int g = 0; g < 8; ++g) { int j = ((g & ~1) << 1) | (g & 1); bf_inv(r[j], r[j + 2], tw4[t + 8 * (j & 1)]); }
    #pragma unroll
    for (int g = 0; g < 8; ++g) { int j = ((g & ~3) << 1) | (g & 3); bf_inv(r[j], r[j + 4], tw[2 * (t + 8 * (j & 3))]); }
    #pragma unroll
    for (int j = 0; j < 8; ++j) bf_inv(r[j], r[j + 8], tw[t + 8 * j]);
}
__device__ __forceinline__ void fftB_fwd(float2 r[16], const float2* tw) {
    #pragma unroll
    for (int g = 0; g < 8; ++g) { int m = ((g & ~3) << 1) | (g & 3); bf_fwd(r[m], r[m + 4], tw[(m & 3) << 4]); }
    #pragma unroll
    for (int g = 0; g < 8; ++g) { int m = ((g & ~1) << 1) | (g & 1); bf_fwd(r[m], r[m + 2], tw[(m & 1) << 5]); }
    #pragma unroll
    for (int g = 0; g < 8; ++g) {
        int m = 2 * g; float2 a = r[m], b = r[m + 1];
        r[m] = make_float2(a.x + b.x, a.y + b.y);
        r[m + 1] = make_float2(a.x - b.x, a.y - b.y);
    }
}
__device__ __forceinline__ void fftB_inv(float2 r[16], const float2* tw) {
    #pragma unroll
    for (int g = 0; g < 8; ++g) {
        int m = 2 * g; float2 a = r[m], b = r[m + 1];
        r[m] = make_float2(a.x + b.x, a.y + b.y);
        r[m + 1] = make_float2(a.x - b.x, a.y - b.y);
    }
    #pragma unroll
    for (int g = 0; g < 8; ++g) { int m = ((g & ~1) << 1) | (g & 1); bf_inv(r[m], r[m + 2], tw[(m & 1) << 5]); }
    #pragma unroll
    for (int g = 0; g < 8; ++g) { int m = ((g & ~3) << 1) | (g & 3); bf_inv(r[m], r[m + 4], tw[(m & 3) << 4]); }
}
__device__ __forceinline__ void init_tw(float2* tw, float2* tw4, float2* tw8) {
    for (int i = threadIdx.x; i < 64; i += blockDim.x) {
        float sn, cs; sincospif(i * (1.0f / 64.0f), &sn, &cs);
        float2 w = make_float2(cs, -sn);
        tw[i] = w;
        if (!(i & 3)) tw4[i >> 2] = w;
        if (!(i & 7)) tw8[i >> 3] = w;
    }
}

// Pass A: pack v1 + i*v2, forward FFT along x then y per (b,z) slab.
// All phases vectorized f32x2 across the line-pair (L, L+64).
__global__ __launch_bounds__(512) void passA(const float* __restrict__ v1,
                                             const float* __restrict__ v2) {
    extern __shared__ char raw[];
    float2* tile = (float2*)raw;
    ull* WX = (ull*)(raw + 128 * 128 * sizeof(float2));
    ull* WY = WX + 88; ull* NY = WY + 88;
    init_vtw(WX, WY, NY);
    const int tid = threadIdx.x, w = tid >> 5, lane = tid & 31;
    const int t = lane & 7, q = (lane >> 3) & 1, h = lane >> 4;
    const int B0 = 2 * (w & 7) + 32 * (w >> 3);
    const int t2 = w & 7, xc = 32 * (w >> 3) + lane;
    const size_t base = (size_t)blockIdx.x * SLAB;
    const ull NEG1 = pk(-1.0f, -1.0f);
    ull Rre[16], Rim[16];
    __syncthreads();
    {   // x-dim, pattern A (gmem in): lines y0, y0+64
        const int y0 = B0 + 16 * q + h, y1 = y0 + 64;
        const float* a0 = v1 + base + y0 * VDIM; const float* a1 = v1 + base + y1 * VDIM;
        const float* b0 = v2 + base + y0 * VDIM; const float* b1 = v2 + base + y1 * VDIM;
        #pragma unroll
        for (int j = 0; j < 16; ++j) { int x = t + 8 * j;
            Rre[j] = pk(a0[x], a1[x]); Rim[j] = pk(b0[x], b1[x]); }
        fftA_fwd_v(Rre, Rim, t, WX, WY, NY, NEG1);
        #pragma unroll
        for (int j = 0; j < 16; ++j) { int x = t + 8 * j; float r0, r1, i0, i1;
            upk(r0, r1, Rre[j]); upk(i0, i1, Rim[j]);
            tile[sidxAC(y0, x)] = make_float2(r0, i0);
            tile[sidxAC(y1, x)] = make_float2(r1, i1); }
    }
    __syncwarp();
    {   // x-dim, pattern B: lines yb0, yb0+64
        const int y0 = B0 + q + 16 * h, y1 = y0 + 64;
        #pragma unroll
        for (int m = 0; m < 16; ++m) { int x = 16 * t + m;
            float2 f0 = tile[sidxAC(y0, x)], f1 = tile[sidxAC(y1, x)];
            Rre[m] = pk(f0.x, f1.x); Rim[m] = pk(f0.y, f1.y); }
        fftB_fwd_v(Rre, Rim, WX, WY, NY, NEG1);
        #pragma unroll
        for (int m = 0; m < 16; ++m) { int x = 16 * t + m; float r0, r1, i0, i1;
            upk(r0, r1, Rre[m]); upk(i0, i1, Rim[m]);
            tile[sidxAC(y0, x)] = make_float2(r0, i0);
            tile[sidxAC(y1, x)] = make_float2(r1, i1); }
    }
    __syncthreads();
    {   // y-dim, pattern A: cols x0, x0+64
        const int x0 = B0 + 16 * q + h, x1 = x0 + 64;
        #pragma unroll
        for (int j = 0; j < 16; ++j) { int y = t + 8 * j;
            float2 f0 = tile[sidxAC(y, x0)], f1 = tile[sidxAC(y, x1)];
            Rre[j] = pk(f0.x, f1.x); Rim[j] = pk(f0.y, f1.y); }
        fftA_fwd_v(Rre, Rim, t, WX, WY, NY, NEG1);
        #pragma unroll
        for (int j = 0; j < 16; ++j) { int y = t + 8 * j; float r0, r1, i0, i1;
            upk(r0, r1, Rre[j]); upk(i0, i1, Rim[j]);
            tile[sidxAC(y, x0)] = make_float2(r0, i0);
            tile[sidxAC(y, x1)] = make_float2(r1, i1); }
    }
    __syncthreads();
    {   // y-dim, pattern B (coalesced gmem out, fp16): cols xc, xc+64
        const int x0 = xc, x1 = xc + 64;
        #pragma unroll
        for (int m = 0; m < 16; ++m) { int y = 16 * t2 + m;
            float2 f0 = tile[sidxAC(y, x0)], f1 = tile[sidxAC(y, x1)];
            Rre[m] = pk(f0.x, f1.x); Rim[m] = pk(f0.y, f1.y); }
        fftB_fwd_v(Rre, Rim, WX, WY, NY, NEG1);
        #pragma unroll
        for (int m = 0; m < 16; ++m) { int y = 16 * t2 + m; float r0, r1, i0, i1;
            upk(r0, r1, Rre[m]); upk(i0, i1, Rim[m]);
            g_Z[base + (size_t)y * VDIM + x0] = __floats2half2_rn(r0, i0);
            g_Z[base + (size_t)y * VDIM + x1] = __floats2half2_rn(r1, i1); }
    }
}

__device__ __forceinline__ float2 Hval(float2 Z, float2 Zn) {
    const float px = Z.x + Zn.x, py = Z.y - Zn.y;   // 2*F1
    const float qx = Z.x - Zn.x, qy = Z.y + Zn.y;   // 2i*F2
    return make_float2(0.25f * (px * qy - py * qx),
                       0.25f * (px * qx + py * qy));
}

// Pass B: unchanged from the passing R8 kernel (scalar path).
__global__ __launch_bounds__(512) void passB() {
    extern __shared__ char raw[];
    float2* tile = (float2*)raw;
    float2* tw = tile + 64 * 128; float2* tw4 = tw + 64; float2* tw8 = tw4 + 16;
    const int xt = blockIdx.x, jy = blockIdx.y, b = blockIdx.z;
    const int jy2 = bneg7(jy);
    const int xt2 = (xt < 2) ? xt : (5 - xt);
    if (jy2 < jy || (jy2 == jy && xt2 < xt)) return;
    const bool full = (jy2 == jy);
    init_tw(tw, tw4, tw8);
    const int tid = threadIdx.x;
    const int t = (tid >> 4) & 7;
    const int l = ((tid >> 7) << 4) | (tid & 15);
    const int xi = l & 31;
    const int gx = (l < 32) ? (32 * xt + xi) : (32 * xt2 + xi);
    const int gy = (l < 32) ? jy : jy2;
    const size_t gb = (size_t)b * VOL + (size_t)gy * VDIM + gx;
    const float SCL = 1.0f / (float)VOL;
    float2 r[16];
    __syncthreads();
    #pragma unroll
    for (int j = 0; j < 16; ++j) r[j] = unpack_h2(g_Z[gb + (size_t)(t + 8 * j) * SLAB]);
    fftA_fwd(r, t, tw, tw4, tw8);
    #pragma unroll
    for (int j = 0; j < 16; ++j) tile[sidxB(l, t + 8 * j)] = r[j];
    __syncthreads();
    #pragma unroll
    for (int m = 0; m < 16; ++m) r[m] = tile[sidxB(l, 16 * t + m)];
    fftB_fwd(r, tw);
    #pragma unroll
    for (int m = 0; m < 16; ++m) tile[sidxB(l, 16 * t + m)] = r[m];
    __syncthreads();
    {
        const int jz = tid & 127, row0 = tid >> 7;
        const int jzn = bneg7(jz);
        #pragma unroll
        for (int k = 0; k < 16; ++k) {
            const int row = row0 + 4 * k;
            const int pr = (row < 32) ? (32 + bneg7(32 * xt + row) - 32 * xt2)
                                      : (bneg7(32 * xt2 + (row - 32)) - 32 * xt);
            r[k] = Hval(tile[sidxB(row, jz)], tile[sidxB(pr, jzn)]);
        }
        __syncthreads();
        #pragma unroll
        for (int k = 0; k < 16; ++k) tile[sidxB(row0 + 4 * k, jz)] = r[k];
    }
    __syncthreads();
    if (full || l < 32) {
        #pragma unroll
        for (int m = 0; m < 16; ++m) r[m] = tile[sidxB(l, 16 * t + m)];
        fftB_inv(r, tw);
        #pragma unroll
        for (int m = 0; m < 16; ++m) tile[sidxB(l, 16 * t + m)] = r[m];
    }
    __syncthreads();
    if (full || l < 32) {
        #pragma unroll
        for (int j = 0; j < 16; ++j) r[j] = tile[sidxB(l, t + 8 * j)];
        fftA_inv(r, t, tw, tw4, tw8);
        #pragma unroll
        for (int j = 0; j < 16; ++j)
            g_Z[gb + (size_t)(t + 8 * j) * SLAB] =
                pack_h2(make_float2(r[j].x * SCL, r[j].y * SCL));
    }
}

// Pass C: gather half-spectrum + mirror conj fill, then inverse y/x FFTs (f32x2).
__global__ __launch_bounds__(512) void passC(float* __restrict__ out) {
    extern __shared__ char raw[];
    float2* tile = (float2*)raw;
    ull* WX = (ull*)(raw + 128 * 128 * sizeof(float2));
    ull* WY = WX + 88; ull* NY = WY + 88;
    init_vtw(WX, WY, NY);
    const int tid = threadIdx.x, w = tid >> 5, lane = tid & 31;
    const int t = lane & 7, q = (lane >> 3) & 1, h = lane >> 4;
    const int B0 = 2 * (w & 7) + 32 * (w >> 3);
    const int t2 = w & 7, xc = 32 * (w >> 3) + lane;
    const size_t base = (size_t)blockIdx.x * SLAB;
    const ull NEG1 = pk(-1.0f, -1.0f);
    ull Rre[16], Rim[16];
    __syncthreads();
    // gather copy-in: load kept rows (jy <= bneg7(jy)); mirror-fill the rest.
    #pragma unroll 1
    for (int jy = w; jy < 128; jy += 16) {
        const int jy2 = bneg7(jy);
        if (jy > jy2) continue;
        #pragma unroll
        for (int k = 0; k < 4; ++k) {
            const int xx = lane + 32 * k;
            const float2 v = unpack_h2(g_Z[base + (size_t)jy * VDIM + xx]);
            tile[sidxAC(jy, xx)] = v;
            if (jy2 != jy) tile[sidxAC(jy2, bneg7(xx))] = make_float2(v.x, -v.y);
        }
    }
    __syncthreads();
    {   // y-dim, pattern B (from smem): cols xc, xc+64
        const int x0 = xc, x1 = xc + 64;
        #pragma unroll
        for (int m = 0; m < 16; ++m) { int y = 16 * t2 + m;
            float2 f0 = tile[sidxAC(y, x0)], f1 = tile[sidxAC(y, x1)];
            Rre[m] = pk(f0.x, f1.x); Rim[m] = pk(f0.y, f1.y); }
        fftB_inv_v(Rre, Rim, WX, WY, NY, NEG1);
        #pragma unroll
        for (int m = 0; m < 16; ++m) { int y = 16 * t2 + m; float r0, r1, i0, i1;
            upk(r0, r1, Rre[m]); upk(i0, i1, Rim[m]);
            tile[sidxAC(y, x0)] = make_float2(r0, i0);
            tile[sidxAC(y, x1)] = make_float2(r1, i1); }
    }
    __syncthreads();
    {   // y-dim, pattern A: cols x0, x0+64
        const int x0 = B0 + 16 * q + h, x1 = x0 + 64;
        #pragma unroll
        for (int j = 0; j < 16; ++j) { int y = t + 8 * j;
            float2 f0 = tile[sidxAC(y, x0)], f1 = tile[sidxAC(y, x1)];
            Rre[j] = pk(f0.x, f1.x); Rim[j] = pk(f0.y, f1.y); }
        fftA_inv_v(Rre, Rim, t, WX, WY, NY, NEG1);
        #pragma unroll
        for (int j = 0; j < 16; ++j) { int y = t + 8 * j; float r0, r1, i0, i1;
            upk(r0, r1, Rre[j]); upk(i0, i1, Rim[j]);
            tile[sidxAC(y, x0)] = make_float2(r0, i0);
            tile[sidxAC(y, x1)] = make_float2(r1, i1); }
    }
    __syncthreads();
    {   // x-dim, pattern B: lines yb0, yb0+64
        const int y0 = B0 + q + 16 * h, y1 = y0 + 64;
        #pragma unroll
        for (int m = 0; m < 16; ++m) { int x = 16 * t + m;
            float2 f0 = tile[sidxAC(y0, x)], f1 = tile[sidxAC(y1, x)];
            Rre[m] = pk(f0.x, f1.x); Rim[m] = pk(f0.y, f1.y); }
        fftB_inv_v(Rre, Rim, WX, WY, NY, NEG1);
        #pragma unroll
        for (int m = 0; m < 16; ++m) { int x = 16 * t + m; float r0, r1, i0, i1;
            upk(r0, r1, Rre[m]); upk(i0, i1, Rim[m]);
            tile[sidxAC(y0, x)] = make_float2(r0, i0);
            tile[sidxAC(y1, x)] = make_float2(r1, i1); }
    }
    __syncwarp();
    {   // x-dim, pattern A -> out: lines y0, y0+64
        const int y0 = B0 + 16 * q + h, y1 = y0 + 64;
        #pragma unroll
        for (int j = 0; j < 16; ++j) { int x = t + 8 * j;
            float2 f0 = tile[sidxAC(y0, x)], f1 = tile[sidxAC(y1, x)];
            Rre[j] = pk(f0.x, f1.x); Rim[j] = pk(f0.y, f1.y); }
        fftA_inv_v(Rre, Rim, t, WX, WY, NY, NEG1);
        #pragma unroll
        for (int j = 0; j < 16; ++j) { int x = t + 8 * j; float r0, r1, i0, i1;
            upk(r0, r1, Rre[j]); upk(i0, i1, Rim[j]);
            out[base + y0 * VDIM + x] = r0;
            out[base + y1 * VDIM + x] = r1; }
    }
}

extern "C" void kernel_launch(void* const* d_in, const int* in_sizes, int n_in,
                              void* d_out, int out_size) {
    const float* v1 = (const float*)d_in[0];
    const float* v2 = (const float*)d_in[1];
    float* out = (float*)d_out;
    const int smAC = 128 * 128 * (int)sizeof(float2) + 3 * 88 * (int)sizeof(ull); // 133,184 B
    const int smB  = (64 * 128 + 64 + 16 + 8) * (int)sizeof(float2);              //  66,240 B
    cudaFuncSetAttribute(passA, cudaFuncAttributeMaxDynamicSharedMemorySize, smAC);
    cudaFuncSetAttribute(passC, cudaFuncAttributeMaxDynamicSharedMemorySize, smAC);
    cudaFuncSetAttribute(passB, cudaFuncAttributeMaxDynamicSharedMemorySize, smB);
    passA<<<NB * VDIM, 512, smAC>>>(v1, v2);
    passB<<<dim3(4, VDIM, NB), 512, smB>>>();
    passC<<<NB * VDIM, 512, smAC>>>(out);
}

// round 10
// speedup vs baseline: 1.0985x; 1.0985x over previous
#include <cuda_runtime.h>
#include <cuda_fp16.h>

#define VDIM 128
#define NB   8
#define SLAB 16384
#define VOL  2097152

// Scratch spectrum stored as half2: 8 * 128^3 * 4 B = 67 MB (static alloc allowed).
__device__ __half2 g_Z[(size_t)NB * VOL];

__device__ __forceinline__ int brev7(int x) { return (int)(__brev((unsigned)x) >> 25); }
__device__ __forceinline__ int bneg7(int j) {
    int k = brev7(j); k = (VDIM - k) & 127; return brev7(k);
}

__device__ __forceinline__ __half2 pack_h2(float2 v) { return __floats2half2_rn(v.x, v.y); }
__device__ __forceinline__ float2 unpack_h2(__half2 h) { return __half22float2(h); }

// passA/C tile swizzle; extra (y&8) term covers y3 for the A' column phases.
__device__ __forceinline__ int sidxAC(int y, int x) {
    int c = x ^ ((x >> 4) & 7) ^ ((x & 1) << 3)
              ^ (y & 7) ^ ((y >> 4) & 7) ^ ((y & 1) << 3) ^ (y & 8);
    return (y << 7) + c;
}
// passB tile swizzle for lane map t=(tid>>4)&7, l=(tid>>7)<<4|(tid&15).
__device__ __forceinline__ int sidxB(int l, int z) {
    int c = z ^ ((z >> 4) & 7) ^ (l & 15);
    return (l << 7) + c;
}

__device__ __forceinline__ float2 cmul(float2 a, float2 w) {
    return make_float2(a.x * w.x - a.y * w.y, a.x * w.y + a.y * w.x);
}
__device__ __forceinline__ float2 cmulc(float2 a, float2 w) {
    return make_float2(a.x * w.x + a.y * w.y, a.y * w.x - a.x * w.y);
}
__device__ __forceinline__ void bf_fwd(float2& ra, float2& rb, float2 w) {
    float2 a = ra, b = rb;
    ra = make_float2(a.x + b.x, a.y + b.y);
    rb = cmul(make_float2(a.x - b.x, a.y - b.y), w);
}
__device__ __forceinline__ void bf_inv(float2& ra, float2& rb, float2 w) {
    float2 a = ra, t = cmulc(rb, w);
    ra = make_float2(a.x + t.x, a.y + t.y);
    rb = make_float2(a.x - t.x, a.y - t.y);
}
__device__ __forceinline__ void bf_triv_fwd(float2& ra, float2& rb) {
    float2 a = ra, b = rb;
    ra = make_float2(a.x + b.x, a.y + b.y);
    rb = make_float2(a.x - b.x, a.y - b.y);
}

// ===== A'/B' split for passA/passC =====
// A': r[k] = x[16*(k>>1) + 2t + (k&1)], stages half = 64, 32, 16.
__device__ __forceinline__ void fftA2_fwd(float2 r[16], int t, const float2* tw) {
    #pragma unroll
    for (int k = 0; k < 8; ++k)
        bf_fwd(r[k], r[k + 8], tw[16 * (k >> 1) + 2 * t + (k & 1)]);
    #pragma unroll
    for (int g = 0; g < 8; ++g) { int k = ((g & ~3) << 1) | (g & 3);
        bf_fwd(r[k], r[k + 4], tw[32 * ((k >> 1) & 1) + 4 * t + 2 * (k & 1)]); }
    #pragma unroll
    for (int g = 0; g < 8; ++g) { int k = ((g & ~1) << 1) | (g & 1);
        bf_fwd(r[k], r[k + 2], tw[8 * t + 4 * (k & 1)]); }
}
__device__ __forceinline__ void fftA2_inv(float2 r[16], int t, const float2* tw) {
    #pragma unroll
    for (int g = 0; g < 8; ++g) { int k = ((g & ~1) << 1) | (g & 1);
        bf_inv(r[k], r[k + 2], tw[8 * t + 4 * (k & 1)]); }
    #pragma unroll
    for (int g = 0; g < 8; ++g) { int k = ((g & ~3) << 1) | (g & 3);
        bf_inv(r[k], r[k + 4], tw[32 * ((k >> 1) & 1) + 4 * t + 2 * (k & 1)]); }
    #pragma unroll
    for (int k = 0; k < 8; ++k)
        bf_inv(r[k], r[k + 8], tw[16 * (k >> 1) + 2 * t + (k & 1)]);
}
// B': r[m] = x[16u + m], stages half = 8, 4, 2, 1.
__device__ __forceinline__ void fftB2_fwd(float2 r[16], const float2* tw) {
    #pragma unroll
    for (int m = 0; m < 8; ++m) bf_fwd(r[m], r[m + 8], tw[8 * m]);
    #pragma unroll
    for (int g = 0; g < 8; ++g) { int m = ((g & ~3) << 1) | (g & 3);
        bf_fwd(r[m], r[m + 4], tw[16 * (m & 3)]); }
    #pragma unroll
    for (int g = 0; g < 8; ++g) { int m = ((g & ~1) << 1) | (g & 1);
        bf_fwd(r[m], r[m + 2], tw[32 * (m & 1)]); }
    #pragma unroll
    for (int g = 0; g < 8; ++g) bf_triv_fwd(r[2 * g], r[2 * g + 1]);
}
__device__ __forceinline__ void fftB2_inv(float2 r[16], const float2* tw) {
    #pragma unroll
    for (int g = 0; g < 8; ++g) bf_triv_fwd(r[2 * g], r[2 * g + 1]);
    #pragma unroll
    for (int g = 0; g < 8; ++g) { int m = ((g & ~1) << 1) | (g & 1);
        bf_inv(r[m], r[m + 2], tw[32 * (m & 1)]); }
    #pragma unroll
    for (int g = 0; g < 8; ++g) { int m = ((g & ~3) << 1) | (g & 3);
        bf_inv(r[m], r[m + 4], tw[16 * (m & 3)]); }
    #pragma unroll
    for (int m = 0; m < 8; ++m) bf_inv(r[m], r[m + 8], tw[8 * m]);
}

// ===== old A/B split (passB only, unchanged from passing R8 kernel) =====
__device__ __forceinline__ void fftA_fwd(float2 r[16], int t, const float2* tw,
                                         const float2* tw4, const float2* tw8) {
    #pragma unroll
    for (int j = 0; j < 8; ++j) bf_fwd(r[j], r[j + 8], tw[t + 8 * j]);
    #pragma unroll
    for (int g = 0; g < 8; ++g) { int j = ((g & ~3) << 1) | (g & 3); bf_fwd(r[j], r[j + 4], tw[2 * (t + 8 * (j & 3))]); }
    #pragma unroll
    for (int g = 0; g < 8; ++g) { int j = ((g & ~1) << 1) | (g & 1); bf_fwd(r[j], r[j + 2], tw4[t + 8 * (j & 1)]); }
    #pragma unroll
    for (int g = 0; g < 8; ++g) { int j = 2 * g; bf_fwd(r[j], r[j + 1], tw8[t]); }
}
__device__ __forceinline__ void fftA_inv(float2 r[16], int t, const float2* tw,
                                         const float2* tw4, const float2* tw8) {
    #pragma unroll
    for (int g = 0; g < 8; ++g) { int j = 2 * g; bf_inv(r[j], r[j + 1], tw8[t]); }
    #pragma unroll
    for (int g = 0; g < 8; ++g) { int j = ((g & ~1) << 1) | (g & 1); bf_inv(r[j], r[j + 2], tw4[t + 8 * (j & 1)]); }
    #pragma unroll
    for (int g = 0; g < 8; ++g) { int j = ((g & ~3) << 1) | (g & 3); bf_inv(r[j], r[j + 4], tw[2 * (t + 8 * (j & 3))]); }
    #pragma unroll
    for (int j = 0; j < 8; ++j) bf_inv(r[j], r[j + 8], tw[t + 8 * j]);
}
__device__ __forceinline__ void fftB_fwd(float2 r[16], const float2* tw) {
    #pragma unroll
    for (int g = 0; g < 8; ++g) { int m = ((g & ~3) << 1) | (g & 3); bf_fwd(r[m], r[m + 4], tw[(m & 3) << 4]); }
    #pragma unroll
    for (int g = 0; g < 8; ++g) { int m = ((g & ~1) << 1) | (g & 1); bf_fwd(r[m], r[m + 2], tw[(m & 1) << 5]); }
    #pragma unroll
    for (int g = 0; g < 8; ++g) bf_triv_fwd(r[2 * g], r[2 * g + 1]);
}
__device__ __forceinline__ void fftB_inv(float2 r[16], const float2* tw) {
    #pragma unroll
    for (int g = 0; g < 8; ++g) bf_triv_fwd(r[2 * g], r[2 * g + 1]);
    #pragma unroll
    for (int g = 0; g < 8; ++g) { int m = ((g & ~1) << 1) | (g & 1); bf_inv(r[m], r[m + 2], tw[(m & 1) << 5]); }
    #pragma unroll
    for (int g = 0; g < 8; ++g) { int m = ((g & ~3) << 1) | (g & 3); bf_inv(r[m], r[m + 4], tw[(m & 3) << 4]); }
}
__device__ __forceinline__ void init_tw(float2* tw, float2* tw4, float2* tw8) {
    for (int i = threadIdx.x; i < 64; i += blockDim.x) {
        float sn, cs; sincospif(i * (1.0f / 64.0f), &sn, &cs);
        float2 w = make_float2(cs, -sn);
        tw[i] = w;
        if (!(i & 3)) tw4[i >> 2] = w;
        if (!(i & 7)) tw8[i >> 3] = w;
    }
}

// Pass A: pack v1 + i*v2, forward FFT along x then y per (b,z) slab.
// A' phases touch gmem/smem as contiguous float2 pairs.
__global__ __launch_bounds__(512) void passA(const float* __restrict__ v1,
                                             const float* __restrict__ v2) {
    extern __shared__ float2 sm[];
    float2* tile = sm;
    float2* tw = sm + 128 * 128; float2* tw4 = tw + 64; float2* tw8 = tw4 + 16;
    init_tw(tw, tw4, tw8);
    const int tid = threadIdx.x, w = tid >> 5, lane = tid & 31;
    const int t = lane & 7, q = (lane >> 3) & 1, h = lane >> 4;
    const int B0 = 2 * (w & 7) + 32 * (w >> 3);
    const int t2 = w & 7, xc = 32 * (w >> 3) + lane;   // map for y-dim B' (gmem)
    const size_t base = (size_t)blockIdx.x * SLAB;
    float2 r[16];
    __syncthreads();
    #pragma unroll 1
    for (int rep = 0; rep < 2; ++rep) {            // x-dim, pattern A' (float2 gmem in)
        const int y = B0 + 16 * q + h + 64 * rep;
        const float* p1 = v1 + base + y * VDIM + 2 * t;
        const float* p2 = v2 + base + y * VDIM + 2 * t;
        #pragma unroll
        for (int j = 0; j < 8; ++j) {
            const float2 a = *(const float2*)(p1 + 16 * j);
            const float2 b = *(const float2*)(p2 + 16 * j);
            r[2 * j]     = make_float2(a.x, b.x);
            r[2 * j + 1] = make_float2(a.y, b.y);
        }
        fftA2_fwd(r, t, tw);
        #pragma unroll
        for (int k = 0; k < 16; ++k)
            tile[sidxAC(y, 16 * (k >> 1) + 2 * t + (k & 1))] = r[k];
    }
    __syncwarp();
    #pragma unroll 1
    for (int rep = 0; rep < 2; ++rep) {            // x-dim, pattern B'
        const int y = B0 + q + 16 * h + 64 * rep;
        #pragma unroll
        for (int m = 0; m < 16; ++m) r[m] = tile[sidxAC(y, 16 * t + m)];
        fftB2_fwd(r, tw);
        #pragma unroll
        for (int m = 0; m < 16; ++m) tile[sidxAC(y, 16 * t + m)] = r[m];
    }
    __syncthreads();
    #pragma unroll 1
    for (int rep = 0; rep < 2; ++rep) {            // y-dim, pattern A'
        const int x = B0 + 16 * q + h + 64 * rep;
        #pragma unroll
        for (int k = 0; k < 16; ++k) r[k] = tile[sidxAC(16 * (k >> 1) + 2 * t + (k & 1), x)];
        fftA2_fwd(r, t, tw);
        #pragma unroll
        for (int k = 0; k < 16; ++k) tile[sidxAC(16 * (k >> 1) + 2 * t + (k & 1), x)] = r[k];
    }
    __syncthreads();
    #pragma unroll 1
    for (int rep = 0; rep < 2; ++rep) {            // y-dim, pattern B' (coalesced out, fp16)
        const int x = xc + 64 * rep;
        #pragma unroll
        for (int m = 0; m < 16; ++m) r[m] = tile[sidxAC(16 * t2 + m, x)];
        fftB2_fwd(r, tw);
        #pragma unroll
        for (int m = 0; m < 16; ++m)
            g_Z[base + (size_t)(16 * t2 + m) * VDIM + x] = pack_h2(r[m]);
    }
}

__device__ __forceinline__ float2 Hval(float2 Z, float2 Zn) {
    const float px = Z.x + Zn.x, py = Z.y - Zn.y;   // 2*F1
    const float qx = Z.x - Zn.x, qy = Z.y + Zn.y;   // 2i*F2
    return make_float2(0.25f * (px * qy - py * qx),
                       0.25f * (px * qx + py * qy));
}

// Pass B: unchanged from the passing R8 kernel.
__global__ __launch_bounds__(512) void passB() {
    extern __shared__ float2 sm[];
    float2* tile = sm;                              // 64 lines x 128 (z)
    float2* tw = sm + 64 * 128; float2* tw4 = tw + 64; float2* tw8 = tw4 + 16;
    const int xt = blockIdx.x, jy = blockIdx.y, b = blockIdx.z;
    const int jy2 = bneg7(jy);
    const int xt2 = (xt < 2) ? xt : (5 - xt);
    if (jy2 < jy || (jy2 == jy && xt2 < xt)) return;
    const bool full = (jy2 == jy);
    init_tw(tw, tw4, tw8);
    const int tid = threadIdx.x;
    const int t = (tid >> 4) & 7;
    const int l = ((tid >> 7) << 4) | (tid & 15);
    const int xi = l & 31;
    const int gx = (l < 32) ? (32 * xt + xi) : (32 * xt2 + xi);
    const int gy = (l < 32) ? jy : jy2;
    const size_t gb = (size_t)b * VOL + (size_t)gy * VDIM + gx;
    const float SCL = 1.0f / (float)VOL;
    float2 r[16];
    __syncthreads();
    #pragma unroll
    for (int j = 0; j < 16; ++j) r[j] = unpack_h2(g_Z[gb + (size_t)(t + 8 * j) * SLAB]);
    fftA_fwd(r, t, tw, tw4, tw8);
    #pragma unroll
    for (int j = 0; j < 16; ++j) tile[sidxB(l, t + 8 * j)] = r[j];
    __syncthreads();
    #pragma unroll
    for (int m = 0; m < 16; ++m) r[m] = tile[sidxB(l, 16 * t + m)];
    fftB_fwd(r, tw);
    #pragma unroll
    for (int m = 0; m < 16; ++m) tile[sidxB(l, 16 * t + m)] = r[m];
    __syncthreads();
    {
        const int jz = tid & 127, row0 = tid >> 7;
        const int jzn = bneg7(jz);
        #pragma unroll
        for (int k = 0; k < 16; ++k) {
            const int row = row0 + 4 * k;
            const int pr = (row < 32) ? (32 + bneg7(32 * xt + row) - 32 * xt2)
                                      : (bneg7(32 * xt2 + (row - 32)) - 32 * xt);
            r[k] = Hval(tile[sidxB(row, jz)], tile[sidxB(pr, jzn)]);
        }
        __syncthreads();
        #pragma unroll
        for (int k = 0; k < 16; ++k) tile[sidxB(row0 + 4 * k, jz)] = r[k];
    }
    __syncthreads();
    if (full || l < 32) {
        #pragma unroll
        for (int m = 0; m < 16; ++m) r[m] = tile[sidxB(l, 16 * t + m)];
        fftB_inv(r, tw);
        #pragma unroll
        for (int m = 0; m < 16; ++m) tile[sidxB(l, 16 * t + m)] = r[m];
    }
    __syncthreads();
    if (full || l < 32) {
        #pragma unroll
        for (int j = 0; j < 16; ++j) r[j] = tile[sidxB(l, t + 8 * j)];
        fftA_inv(r, t, tw, tw4, tw8);
        #pragma unroll
        for (int j = 0; j < 16; ++j)
            g_Z[gb + (size_t)(t + 8 * j) * SLAB] =
                pack_h2(make_float2(r[j].x * SCL, r[j].y * SCL));
    }
}

// Pass C: gather half-spectrum + mirror conj fill, inverse y then x, float2 out.
__global__ __launch_bounds__(512) void passC(float* __restrict__ out) {
    extern __shared__ float2 sm[];
    float2* tile = sm;
    float2* tw = sm + 128 * 128; float2* tw4 = tw + 64; float2* tw8 = tw4 + 16;
    init_tw(tw, tw4, tw8);
    const int tid = threadIdx.x, w = tid >> 5, lane = tid & 31;
    const int t = lane & 7, q = (lane >> 3) & 1, h = lane >> 4;
    const int B0 = 2 * (w & 7) + 32 * (w >> 3);
    const int t2 = w & 7, xc = 32 * (w >> 3) + lane;
    const size_t base = (size_t)blockIdx.x * SLAB;
    float2 r[16];
    __syncthreads();
    // gather copy-in: load kept rows (jy <= bneg7(jy)); mirror-fill the rest.
    #pragma unroll 1
    for (int jy = w; jy < 128; jy += 16) {
        const int jy2 = bneg7(jy);
        if (jy > jy2) continue;
        #pragma unroll
        for (int k = 0; k < 4; ++k) {
            const int xx = lane + 32 * k;
            const float2 v = unpack_h2(g_Z[base + (size_t)jy * VDIM + xx]);
            tile[sidxAC(jy, xx)] = v;
            if (jy2 != jy) tile[sidxAC(jy2, bneg7(xx))] = make_float2(v.x, -v.y);
        }
    }
    __syncthreads();
    #pragma unroll 1
    for (int rep = 0; rep < 2; ++rep) {            // y-dim, pattern B' (from smem)
        const int x = xc + 64 * rep;
        #pragma unroll
        for (int m = 0; m < 16; ++m) r[m] = tile[sidxAC(16 * t2 + m, x)];
        fftB2_inv(r, tw);
        #pragma unroll
        for (int m = 0; m < 16; ++m) tile[sidxAC(16 * t2 + m, x)] = r[m];
    }
    __syncthreads();
    #pragma unroll 1
    for (int rep = 0; rep < 2; ++rep) {            // y-dim, pattern A'
        const int x = B0 + 16 * q + h + 64 * rep;
        #pragma unroll
        for (int k = 0; k < 16; ++k) r[k] = tile[sidxAC(16 * (k >> 1) + 2 * t + (k & 1), x)];
        fftA2_inv(r, t, tw);
        #pragma unroll
        for (int k = 0; k < 16; ++k) tile[sidxAC(16 * (k >> 1) + 2 * t + (k & 1), x)] = r[k];
    }
    __syncthreads();
    #pragma unroll 1
    for (int rep = 0; rep < 2; ++rep) {            // x-dim, pattern B'
        const int y = B0 + q + 16 * h + 64 * rep;
        #pragma unroll
        for (int m = 0; m < 16; ++m) r[m] = tile[sidxAC(y, 16 * t + m)];
        fftB2_inv(r, tw);
        #pragma unroll
        for (int m = 0; m < 16; ++m) tile[sidxAC(y, 16 * t + m)] = r[m];
    }
    __syncwarp();
    #pragma unroll 1
    for (int rep = 0; rep < 2; ++rep) {            // x-dim, pattern A' -> float2 out
        const int y = B0 + 16 * q + h + 64 * rep;
        #pragma unroll
        for (int k = 0; k < 16; ++k) r[k] = tile[sidxAC(y, 16 * (k >> 1) + 2 * t + (k & 1))];
        fftA2_inv(r, t, tw);
        float* po = out + base + y * VDIM + 2 * t;
        #pragma unroll
        for (int j = 0; j < 8; ++j)
            *(float2*)(po + 16 * j) = make_float2(r[2 * j].x, r[2 * j + 1].x);
    }
}

extern "C" void kernel_launch(void* const* d_in, const int* in_sizes, int n_in,
                              void* d_out, int out_size) {
    const float* v1 = (const float*)d_in[0];
    const float* v2 = (const float*)d_in[1];
    float* out = (float*)d_out;
    const int smAC = (128 * 128 + 64 + 16 + 8) * (int)sizeof(float2);  // 131,776 B
    const int smB  = (64 * 128 + 64 + 16 + 8) * (int)sizeof(float2);   //  66,240 B
    cudaFuncSetAttribute(passA, cudaFuncAttributeMaxDynamicSharedMemorySize, smAC);
    cudaFuncSetAttribute(passC, cudaFuncAttributeMaxDynamicSharedMemorySize, smAC);
    cudaFuncSetAttribute(passB, cudaFuncAttributeMaxDynamicSharedMemorySize, smB);
    passA<<<NB * VDIM, 512, smAC>>>(v1, v2);
    passB<<<dim3(4, VDIM, NB), 512, smB>>>();
    passC<<<NB * VDIM, 512, smAC>>>(out);
}

// round 11
// speedup vs baseline: 1.1861x; 1.0797x over previous
#include <cuda_runtime.h>
#include <cuda_fp16.h>

#define VDIM 128
#define NB   8
#define SLAB 16384
#define VOL  2097152

// Scratch spectrum stored as half2: 8 * 128^3 * 4 B = 67 MB (static alloc allowed).
__device__ __half2 g_Z[(size_t)NB * VOL];

__device__ __forceinline__ int brev7(int x) { return (int)(__brev((unsigned)x) >> 25); }
__device__ __forceinline__ int bneg7(int j) {
    int k = brev7(j); k = (VDIM - k) & 127; return brev7(k);
}

__device__ __forceinline__ __half2 pack_h2(float2 v) { return __floats2half2_rn(v.x, v.y); }
__device__ __forceinline__ float2 unpack_h2(__half2 h) { return __half22float2(h); }

// passA/C tile swizzle; extra (y&8) term covers y3 for the A' column phases.
__device__ __forceinline__ int sidxAC(int y, int x) {
    int c = x ^ ((x >> 4) & 7) ^ ((x & 1) << 3)
              ^ (y & 7) ^ ((y >> 4) & 7) ^ ((y & 1) << 3) ^ (y & 8);
    return (y << 7) + c;
}
// passB tile swizzle.
__device__ __forceinline__ int sidxB(int l, int z) {
    int c = z ^ ((z >> 4) & 7) ^ (l & 15);
    return (l << 7) + c;
}

__device__ __forceinline__ float2 cmul(float2 a, float2 w) {
    return make_float2(a.x * w.x - a.y * w.y, a.x * w.y + a.y * w.x);
}
__device__ __forceinline__ float2 cmulc(float2 a, float2 w) {
    return make_float2(a.x * w.x + a.y * w.y, a.y * w.x - a.x * w.y);
}
__device__ __forceinline__ void bf_fwd(float2& ra, float2& rb, float2 w) {
    float2 a = ra, b = rb;
    ra = make_float2(a.x + b.x, a.y + b.y);
    rb = cmul(make_float2(a.x - b.x, a.y - b.y), w);
}
__device__ __forceinline__ void bf_inv(float2& ra, float2& rb, float2 w) {
    float2 a = ra, t = cmulc(rb, w);
    ra = make_float2(a.x + t.x, a.y + t.y);
    rb = make_float2(a.x - t.x, a.y - t.y);
}
__device__ __forceinline__ void bf_triv_fwd(float2& ra, float2& rb) {
    float2 a = ra, b = rb;
    ra = make_float2(a.x + b.x, a.y + b.y);
    rb = make_float2(a.x - b.x, a.y - b.y);
}

// ===== A'/B' split (passA/passC) =====
__device__ __forceinline__ void fftA2_fwd(float2 r[16], int t, const float2* tw) {
    #pragma unroll
    for (int k = 0; k < 8; ++k)
        bf_fwd(r[k], r[k + 8], tw[16 * (k >> 1) + 2 * t + (k & 1)]);
    #pragma unroll
    for (int g = 0; g < 8; ++g) { int k = ((g & ~3) << 1) | (g & 3);
        bf_fwd(r[k], r[k + 4], tw[32 * ((k >> 1) & 1) + 4 * t + 2 * (k & 1)]); }
    #pragma unroll
    for (int g = 0; g < 8; ++g) { int k = ((g & ~1) << 1) | (g & 1);
        bf_fwd(r[k], r[k + 2], tw[8 * t + 4 * (k & 1)]); }
}
__device__ __forceinline__ void fftA2_inv(float2 r[16], int t, const float2* tw) {
    #pragma unroll
    for (int g = 0; g < 8; ++g) { int k = ((g & ~1) << 1) | (g & 1);
        bf_inv(r[k], r[k + 2], tw[8 * t + 4 * (k & 1)]); }
    #pragma unroll
    for (int g = 0; g < 8; ++g) { int k = ((g & ~3) << 1) | (g & 3);
        bf_inv(r[k], r[k + 4], tw[32 * ((k >> 1) & 1) + 4 * t + 2 * (k & 1)]); }
    #pragma unroll
    for (int k = 0; k < 8; ++k)
        bf_inv(r[k], r[k + 8], tw[16 * (k >> 1) + 2 * t + (k & 1)]);
}
__device__ __forceinline__ void fftB2_fwd(float2 r[16], const float2* tw) {
    #pragma unroll
    for (int m = 0; m < 8; ++m) bf_fwd(r[m], r[m + 8], tw[8 * m]);
    #pragma unroll
    for (int g = 0; g < 8; ++g) { int m = ((g & ~3) << 1) | (g & 3);
        bf_fwd(r[m], r[m + 4], tw[16 * (m & 3)]); }
    #pragma unroll
    for (int g = 0; g < 8; ++g) { int m = ((g & ~1) << 1) | (g & 1);
        bf_fwd(r[m], r[m + 2], tw[32 * (m & 1)]); }
    #pragma unroll
    for (int g = 0; g < 8; ++g) bf_triv_fwd(r[2 * g], r[2 * g + 1]);
}
__device__ __forceinline__ void fftB2_inv(float2 r[16], const float2* tw) {
    #pragma unroll
    for (int g = 0; g < 8; ++g) bf_triv_fwd(r[2 * g], r[2 * g + 1]);
    #pragma unroll
    for (int g = 0; g < 8; ++g) { int m = ((g & ~1) << 1) | (g & 1);
        bf_inv(r[m], r[m + 2], tw[32 * (m & 1)]); }
    #pragma unroll
    for (int g = 0; g < 8; ++g) { int m = ((g & ~3) << 1) | (g & 3);
        bf_inv(r[m], r[m + 4], tw[16 * (m & 3)]); }
    #pragma unroll
    for (int m = 0; m < 8; ++m) bf_inv(r[m], r[m + 8], tw[8 * m]);
}

// ===== old A/B split (passB) =====
__device__ __forceinline__ void fftA_fwd(float2 r[16], int t, const float2* tw,
                                         const float2* tw4, const float2* tw8) {
    #pragma unroll
    for (int j = 0; j < 8; ++j) bf_fwd(r[j], r[j + 8], tw[t + 8 * j]);
    #pragma unroll
    for (int g = 0; g < 8; ++g) { int j = ((g & ~3) << 1) | (g & 3); bf_fwd(r[j], r[j + 4], tw[2 * (t + 8 * (j & 3))]); }
    #pragma unroll
    for (int g = 0; g < 8; ++g) { int j = ((g & ~1) << 1) | (g & 1); bf_fwd(r[j], r[j + 2], tw4[t + 8 * (j & 1)]); }
    #pragma unroll
    for (int g = 0; g < 8; ++g) { int j = 2 * g; bf_fwd(r[j], r[j + 1], tw8[t]); }
}
__device__ __forceinline__ void fftA_inv(float2 r[16], int t, const float2* tw,
                                         const float2* tw4, const float2* tw8) {
    #pragma unroll
    for (int g = 0; g < 8; ++g) { int j = 2 * g; bf_inv(r[j], r[j + 1], tw8[t]); }
    #pragma unroll
    for (int g = 0; g < 8; ++g) { int j = ((g & ~1) << 1) | (g & 1); bf_inv(r[j], r[j + 2], tw4[t + 8 * (j & 1)]); }
    #pragma unroll
    for (int g = 0; g < 8; ++g) { int j = ((g & ~3) << 1) | (g & 3); bf_inv(r[j], r[j + 4], tw[2 * (t + 8 * (j & 3))]); }
    #pragma unroll
    for (int j = 0; j < 8; ++j) bf_inv(r[j], r[j + 8], tw[t + 8 * j]);
}
__device__ __forceinline__ void fftB_fwd(float2 r[16], const float2* tw) {
    #pragma unroll
    for (int g = 0; g < 8; ++g) { int m = ((g & ~3) << 1) | (g & 3); bf_fwd(r[m], r[m + 4], tw[(m & 3) << 4]); }
    #pragma unroll
    for (int g = 0; g < 8; ++g) { int m = ((g & ~1) << 1) | (g & 1); bf_fwd(r[m], r[m + 2], tw[(m & 1) << 5]); }
    #pragma unroll
    for (int g = 0; g < 8; ++g) bf_triv_fwd(r[2 * g], r[2 * g + 1]);
}
__device__ __forceinline__ void fftB_inv(float2 r[16], const float2* tw) {
    #pragma unroll
    for (int g = 0; g < 8; ++g) bf_triv_fwd(r[2 * g], r[2 * g + 1]);
    #pragma unroll
    for (int g = 0; g < 8; ++g) { int m = ((g & ~1) << 1) | (g & 1); bf_inv(r[m], r[m + 2], tw[(m & 1) << 5]); }
    #pragma unroll
    for (int g = 0; g < 8; ++g) { int m = ((g & ~3) << 1) | (g & 3); bf_inv(r[m], r[m + 4], tw[(m & 3) << 4]); }
}
__device__ __forceinline__ void init_tw(float2* tw, float2* tw4, float2* tw8) {
    for (int i = threadIdx.x; i < 64; i += blockDim.x) {
        float sn, cs; sincospif(i * (1.0f / 64.0f), &sn, &cs);
        float2 w = make_float2(cs, -sn);
        tw[i] = w;
        if (!(i & 3)) tw4[i >> 2] = w;
        if (!(i & 7)) tw8[i >> 3] = w;
    }
}

// Pass A: pack v1 + i*v2, forward FFT along x then y per (b,z) slab.
__global__ __launch_bounds__(512) void passA(const float* __restrict__ v1,
                                             const float* __restrict__ v2) {
    extern __shared__ float2 sm[];
    float2* tile = sm;
    float2* tw = sm + 128 * 128; float2* tw4 = tw + 64; float2* tw8 = tw4 + 16;
    init_tw(tw, tw4, tw8);
    const int tid = threadIdx.x, w = tid >> 5, lane = tid & 31;
    const int t = lane & 7, q = (lane >> 3) & 1, h = lane >> 4;
    const int B0 = 2 * (w & 7) + 32 * (w >> 3);
    const int t2 = w & 7, xc = 32 * (w >> 3) + lane;
    const size_t base = (size_t)blockIdx.x * SLAB;
    float2 r[16];
    __syncthreads();
    #pragma unroll 1
    for (int rep = 0; rep < 2; ++rep) {            // x-dim, pattern A' (float2 gmem in)
        const int y = B0 + 16 * q + h + 64 * rep;
        const float* p1 = v1 + base + y * VDIM + 2 * t;
        const float* p2 = v2 + base + y * VDIM + 2 * t;
        #pragma unroll
        for (int j = 0; j < 8; ++j) {
            const float2 a = *(const float2*)(p1 + 16 * j);
            const float2 b = *(const float2*)(p2 + 16 * j);
            r[2 * j]     = make_float2(a.x, b.x);
            r[2 * j + 1] = make_float2(a.y, b.y);
        }
        fftA2_fwd(r, t, tw);
        #pragma unroll
        for (int k = 0; k < 16; ++k)
            tile[sidxAC(y, 16 * (k >> 1) + 2 * t + (k & 1))] = r[k];
    }
    __syncwarp();
    #pragma unroll 1
    for (int rep = 0; rep < 2; ++rep) {            // x-dim, pattern B'
        const int y = B0 + q + 16 * h + 64 * rep;
        #pragma unroll
        for (int m = 0; m < 16; ++m) r[m] = tile[sidxAC(y, 16 * t + m)];
        fftB2_fwd(r, tw);
        #pragma unroll
        for (int m = 0; m < 16; ++m) tile[sidxAC(y, 16 * t + m)] = r[m];
    }
    __syncthreads();
    #pragma unroll 1
    for (int rep = 0; rep < 2; ++rep) {            // y-dim, pattern A'
        const int x = B0 + 16 * q + h + 64 * rep;
        #pragma unroll
        for (int k = 0; k < 16; ++k) r[k] = tile[sidxAC(16 * (k >> 1) + 2 * t + (k & 1), x)];
        fftA2_fwd(r, t, tw);
        #pragma unroll
        for (int k = 0; k < 16; ++k) tile[sidxAC(16 * (k >> 1) + 2 * t + (k & 1), x)] = r[k];
    }
    __syncthreads();
    #pragma unroll 1
    for (int rep = 0; rep < 2; ++rep) {            // y-dim, pattern B' (coalesced out, fp16)
        const int x = xc + 64 * rep;
        #pragma unroll
        for (int m = 0; m < 16; ++m) r[m] = tile[sidxAC(16 * t2 + m, x)];
        fftB2_fwd(r, tw);
        #pragma unroll
        for (int m = 0; m < 16; ++m)
            g_Z[base + (size_t)(16 * t2 + m) * VDIM + x] = pack_h2(r[m]);
    }
}

__device__ __forceinline__ float2 Hval(float2 Z, float2 Zn) {
    const float px = Z.x + Zn.x, py = Z.y - Zn.y;   // 2*F1
    const float qx = Z.x - Zn.x, qy = Z.y + Zn.y;   // 2i*F2
    return make_float2(0.25f * (px * qy - py * qx),
                       0.25f * (px * qx + py * qy));
}

// Pass B: 256 threads, 2 CTAs/SM. Each thread sequentially handles slot l0 (tileA)
// and l0+32 (tileB). Pointwise uses hazard-free quad ownership (no extra barrier).
__global__ __launch_bounds__(256, 2) void passB() {
    extern __shared__ float2 sm[];
    float2* tile = sm;                              // 64 lines x 128 (z)
    float2* tw = sm + 64 * 128; float2* tw4 = tw + 64; float2* tw8 = tw4 + 16;
    const int xt = blockIdx.x, jy = blockIdx.y, b = blockIdx.z;
    const int jy2 = bneg7(jy);
    const int xt2 = (xt < 2) ? xt : (5 - xt);
    if (jy2 < jy || (jy2 == jy && xt2 < xt)) return;
    const bool full = (jy2 == jy);
    init_tw(tw, tw4, tw8);
    const int tid = threadIdx.x;
    const int t = (tid >> 4) & 7;
    const int l0 = ((tid >> 7) << 4) | (tid & 15);  // 0..31 (tileA row)
    const int l1 = l0 + 32;                          // tileB row
    const size_t vb = (size_t)b * VOL;
    const size_t gb0 = vb + (size_t)jy  * VDIM + (32 * xt  + l0);
    const size_t gb1 = vb + (size_t)jy2 * VDIM + (32 * xt2 + l0);
    const float SCL = 1.0f / (float)VOL;
    float2 r[16];
    __syncthreads();
    // forward z-FFT pattern A: slot0 (tileA) then slot1 (tileB)
    #pragma unroll
    for (int j = 0; j < 16; ++j) r[j] = unpack_h2(g_Z[gb0 + (size_t)(t + 8 * j) * SLAB]);
    fftA_fwd(r, t, tw, tw4, tw8);
    #pragma unroll
    for (int j = 0; j < 16; ++j) tile[sidxB(l0, t + 8 * j)] = r[j];
    #pragma unroll
    for (int j = 0; j < 16; ++j) r[j] = unpack_h2(g_Z[gb1 + (size_t)(t + 8 * j) * SLAB]);
    fftA_fwd(r, t, tw, tw4, tw8);
    #pragma unroll
    for (int j = 0; j < 16; ++j) tile[sidxB(l1, t + 8 * j)] = r[j];
    __syncthreads();
    // forward z-FFT pattern B: both slots
    #pragma unroll
    for (int m = 0; m < 16; ++m) r[m] = tile[sidxB(l0, 16 * t + m)];
    fftB_fwd(r, tw);
    #pragma unroll
    for (int m = 0; m < 16; ++m) tile[sidxB(l0, 16 * t + m)] = r[m];
    #pragma unroll
    for (int m = 0; m < 16; ++m) r[m] = tile[sidxB(l1, 16 * t + m)];
    fftB_fwd(r, tw);
    #pragma unroll
    for (int m = 0; m < 16; ++m) tile[sidxB(l1, 16 * t + m)] = r[m];
    __syncthreads();
    // pointwise, quad ownership: thread handles (row in tileA, jz<=jzn) quads;
    // quads are disjoint (partner-row is a bijection), so no hazards, no barrier.
    #pragma unroll 1
    for (int i = tid; i < 32 * 128; i += 256) {
        const int jz = i & 127, row = i >> 7;
        const int jzn = bneg7(jz);
        if (jzn < jz) continue;
        const int pr = 32 + bneg7(32 * xt + row) - 32 * xt2;
        const float2 a1 = tile[sidxB(row, jz)], a2 = tile[sidxB(row, jzn)];
        const float2 b1 = tile[sidxB(pr, jz)],  b2 = tile[sidxB(pr, jzn)];
        tile[sidxB(row, jz)]  = Hval(a1, b2);
        tile[sidxB(pr, jz)]   = Hval(b1, a2);
        tile[sidxB(row, jzn)] = Hval(a2, b1);
        tile[sidxB(pr, jzn)]  = Hval(b2, a1);
    }
    __syncthreads();
    // inverse z-FFT pattern B: slot0 always; slot1 only for self-paired rows
    #pragma unroll
    for (int m = 0; m < 16; ++m) r[m] = tile[sidxB(l0, 16 * t + m)];
    fftB_inv(r, tw);
    #pragma unroll
    for (int m = 0; m < 16; ++m) tile[sidxB(l0, 16 * t + m)] = r[m];
    if (full) {
        #pragma unroll
        for (int m = 0; m < 16; ++m) r[m] = tile[sidxB(l1, 16 * t + m)];
        fftB_inv(r, tw);
        #pragma unroll
        for (int m = 0; m < 16; ++m) tile[sidxB(l1, 16 * t + m)] = r[m];
    }
    __syncthreads();
    // inverse z-FFT pattern A + scaled fp16 store
    #pragma unroll
    for (int j = 0; j < 16; ++j) r[j] = tile[sidxB(l0, t + 8 * j)];
    fftA_inv(r, t, tw, tw4, tw8);
    #pragma unroll
    for (int j = 0; j < 16; ++j)
        g_Z[gb0 + (size_t)(t + 8 * j) * SLAB] =
            pack_h2(make_float2(r[j].x * SCL, r[j].y * SCL));
    if (full) {
        #pragma unroll
        for (int j = 0; j < 16; ++j) r[j] = tile[sidxB(l1, t + 8 * j)];
        fftA_inv(r, t, tw, tw4, tw8);
        #pragma unroll
        for (int j = 0; j < 16; ++j)
            g_Z[gb1 + (size_t)(t + 8 * j) * SLAB] =
                pack_h2(make_float2(r[j].x * SCL, r[j].y * SCL));
    }
}

// Pass C: gather half-spectrum + mirror conj fill, inverse y then x, float2 out.
__global__ __launch_bounds__(512) void passC(float* __restrict__ out) {
    extern __shared__ float2 sm[];
    float2* tile = sm;
    float2* tw = sm + 128 * 128; float2* tw4 = tw + 64; float2* tw8 = tw4 + 16;
    init_tw(tw, tw4, tw8);
    const int tid = threadIdx.x, w = tid >> 5, lane = tid & 31;
    const int t = lane & 7, q = (lane >> 3) & 1, h = lane >> 4;
    const int B0 = 2 * (w & 7) + 32 * (w >> 3);
    const int t2 = w & 7, xc = 32 * (w >> 3) + lane;
    const size_t base = (size_t)blockIdx.x * SLAB;
    float2 r[16];
    __syncthreads();
    // gather copy-in: load kept rows (jy <= bneg7(jy)); mirror-fill the rest.
    #pragma unroll 1
    for (int jy = w; jy < 128; jy += 16) {
        const int jy2 = bneg7(jy);
        if (jy > jy2) continue;
        #pragma unroll
        for (int k = 0; k < 4; ++k) {
            const int xx = lane + 32 * k;
            const float2 v = unpack_h2(g_Z[base + (size_t)jy * VDIM + xx]);
            tile[sidxAC(jy, xx)] = v;
            if (jy2 != jy) tile[sidxAC(jy2, bneg7(xx))] = make_float2(v.x, -v.y);
        }
    }
    __syncthreads();
    #pragma unroll 1
    for (int rep = 0; rep < 2; ++rep) {            // y-dim, pattern B' (from smem)
        const int x = xc + 64 * rep;
        #pragma unroll
        for (int m = 0; m < 16; ++m) r[m] = tile[sidxAC(16 * t2 + m, x)];
        fftB2_inv(r, tw);
        #pragma unroll
        for (int m = 0; m < 16; ++m) tile[sidxAC(16 * t2 + m, x)] = r[m];
    }
    __syncthreads();
    #pragma unroll 1
    for (int rep = 0; rep < 2; ++rep) {            // y-dim, pattern A'
        const int x = B0 + 16 * q + h + 64 * rep;
        #pragma unroll
        for (int k = 0; k < 16; ++k) r[k] = tile[sidxAC(16 * (k >> 1) + 2 * t + (k & 1), x)];
        fftA2_inv(r, t, tw);
        #pragma unroll
        for (int k = 0; k < 16; ++k) tile[sidxAC(16 * (k >> 1) + 2 * t + (k & 1), x)] = r[k];
    }
    __syncthreads();
    #pragma unroll 1
    for (int rep = 0; rep < 2; ++rep) {            // x-dim, pattern B'
        const int y = B0 + q + 16 * h + 64 * rep;
        #pragma unroll
        for (int m = 0; m < 16; ++m) r[m] = tile[sidxAC(y, 16 * t + m)];
        fftB2_inv(r, tw);
        #pragma unroll
        for (int m = 0; m < 16; ++m) tile[sidxAC(y, 16 * t + m)] = r[m];
    }
    __syncwarp();
    #pragma unroll 1
    for (int rep = 0; rep < 2; ++rep) {            // x-dim, pattern A' -> float2 out
        const int y = B0 + 16 * q + h + 64 * rep;
        #pragma unroll
        for (int k = 0; k < 16; ++k) r[k] = tile[sidxAC(y, 16 * (k >> 1) + 2 * t + (k & 1))];
        fftA2_inv(r, t, tw);
        float* po = out + base + y * VDIM + 2 * t;
        #pragma unroll
        for (int j = 0; j < 8; ++j)
            *(float2*)(po + 16 * j) = make_float2(r[2 * j].x, r[2 * j + 1].x);
    }
}

extern "C" void kernel_launch(void* const* d_in, const int* in_sizes, int n_in,
                              void* d_out, int out_size) {
    const float* v1 = (const float*)d_in[0];
    const float* v2 = (const float*)d_in[1];
    float* out = (float*)d_out;
    const int smAC = (128 * 128 + 64 + 16 + 8) * (int)sizeof(float2);  // 131,776 B
    const int smB  = (64 * 128 + 64 + 16 + 8) * (int)sizeof(float2);   //  66,240 B
    cudaFuncSetAttribute(passA, cudaFuncAttributeMaxDynamicSharedMemorySize, smAC);
    cudaFuncSetAttribute(passC, cudaFuncAttributeMaxDynamicSharedMemorySize, smAC);
    cudaFuncSetAttribute(passB, cudaFuncAttributeMaxDynamicSharedMemorySize, smB);
    passA<<<NB * VDIM, 512, smAC>>>(v1, v2);
    passB<<<dim3(4, VDIM, NB), 256, smB>>>();
    passC<<<NB * VDIM, 512, smAC>>>(out);
}

// round 12
// speedup vs baseline: 1.3014x; 1.0972x over previous
#include <cuda_runtime.h>
#include <cuda_fp16.h>

#define VDIM 128
#define NB   8
#define SLAB 16384
#define VOL  2097152

// Scratch spectrum stored as half2: 8 * 128^3 * 4 B = 67 MB (static alloc allowed).
__device__ __half2 g_Z[(size_t)NB * VOL];

__device__ __forceinline__ int brev7(int x) { return (int)(__brev((unsigned)x) >> 25); }
__device__ __forceinline__ int bneg7(int j) {
    int k = brev7(j); k = (VDIM - k) & 127; return brev7(k);
}

__device__ __forceinline__ __half2 pack_h2(float2 v) { return __floats2half2_rn(v.x, v.y); }
__device__ __forceinline__ float2 unpack_h2(__half2 h) { return __half22float2(h); }

// passA/C half2-tile swizzle: 32-bit/32-lane bank-bijective for all phases.
// (extra (y&1)<<4 term makes c4 vary; verified per-phase over GF(2).)
__device__ __forceinline__ int sidxAC(int y, int x) {
    int c = x ^ ((x >> 4) & 7) ^ ((x & 1) << 3)
              ^ (y & 7) ^ ((y >> 4) & 7) ^ ((y & 1) << 3) ^ (y & 8) ^ ((y & 1) << 4);
    return (y << 7) + c;
}
// passB tile swizzle (fp32 tile, unchanged).
__device__ __forceinline__ int sidxB(int l, int z) {
    int c = z ^ ((z >> 4) & 7) ^ (l & 15);
    return (l << 7) + c;
}

__device__ __forceinline__ float2 cmul(float2 a, float2 w) {
    return make_float2(a.x * w.x - a.y * w.y, a.x * w.y + a.y * w.x);
}
__device__ __forceinline__ float2 cmulc(float2 a, float2 w) {
    return make_float2(a.x * w.x + a.y * w.y, a.y * w.x - a.x * w.y);
}
__device__ __forceinline__ void bf_fwd(float2& ra, float2& rb, float2 w) {
    float2 a = ra, b = rb;
    ra = make_float2(a.x + b.x, a.y + b.y);
    rb = cmul(make_float2(a.x - b.x, a.y - b.y), w);
}
__device__ __forceinline__ void bf_inv(float2& ra, float2& rb, float2 w) {
    float2 a = ra, t = cmulc(rb, w);
    ra = make_float2(a.x + t.x, a.y + t.y);
    rb = make_float2(a.x - t.x, a.y - t.y);
}
__device__ __forceinline__ void bf_triv_fwd(float2& ra, float2& rb) {
    float2 a = ra, b = rb;
    ra = make_float2(a.x + b.x, a.y + b.y);
    rb = make_float2(a.x - b.x, a.y - b.y);
}

// ===== A'/B' split (passA/passC) =====
__device__ __forceinline__ void fftA2_fwd(float2 r[16], int t, const float2* tw) {
    #pragma unroll
    for (int k = 0; k < 8; ++k)
        bf_fwd(r[k], r[k + 8], tw[16 * (k >> 1) + 2 * t + (k & 1)]);
    #pragma unroll
    for (int g = 0; g < 8; ++g) { int k = ((g & ~3) << 1) | (g & 3);
        bf_fwd(r[k], r[k + 4], tw[32 * ((k >> 1) & 1) + 4 * t + 2 * (k & 1)]); }
    #pragma unroll
    for (int g = 0; g < 8; ++g) { int k = ((g & ~1) << 1) | (g & 1);
        bf_fwd(r[k], r[k + 2], tw[8 * t + 4 * (k & 1)]); }
}
__device__ __forceinline__ void fftA2_inv(float2 r[16], int t, const float2* tw) {
    #pragma unroll
    for (int g = 0; g < 8; ++g) { int k = ((g & ~1) << 1) | (g & 1);
        bf_inv(r[k], r[k + 2], tw[8 * t + 4 * (k & 1)]); }
    #pragma unroll
    for (int g = 0; g < 8; ++g) { int k = ((g & ~3) << 1) | (g & 3);
        bf_inv(r[k], r[k + 4], tw[32 * ((k >> 1) & 1) + 4 * t + 2 * (k & 1)]); }
    #pragma unroll
    for (int k = 0; k < 8; ++k)
        bf_inv(r[k], r[k + 8], tw[16 * (k >> 1) + 2 * t + (k & 1)]);
}
__device__ __forceinline__ void fftB2_fwd(float2 r[16], const float2* tw) {
    #pragma unroll
    for (int m = 0; m < 8; ++m) bf_fwd(r[m], r[m + 8], tw[8 * m]);
    #pragma unroll
    for (int g = 0; g < 8; ++g) { int m = ((g & ~3) << 1) | (g & 3);
        bf_fwd(r[m], r[m + 4], tw[16 * (m & 3)]); }
    #pragma unroll
    for (int g = 0; g < 8; ++g) { int m = ((g & ~1) << 1) | (g & 1);
        bf_fwd(r[m], r[m + 2], tw[32 * (m & 1)]); }
    #pragma unroll
    for (int g = 0; g < 8; ++g) bf_triv_fwd(r[2 * g], r[2 * g + 1]);
}
__device__ __forceinline__ void fftB2_inv(float2 r[16], const float2* tw) {
    #pragma unroll
    for (int g = 0; g < 8; ++g) bf_triv_fwd(r[2 * g], r[2 * g + 1]);
    #pragma unroll
    for (int g = 0; g < 8; ++g) { int m = ((g & ~1) << 1) | (g & 1);
        bf_inv(r[m], r[m + 2], tw[32 * (m & 1)]); }
    #pragma unroll
    for (int g = 0; g < 8; ++g) { int m = ((g & ~3) << 1) | (g & 3);
        bf_inv(r[m], r[m + 4], tw[16 * (m & 3)]); }
    #pragma unroll
    for (int m = 0; m < 8; ++m) bf_inv(r[m], r[m + 8], tw[8 * m]);
}

// ===== old A/B split (passB) =====
__device__ __forceinline__ void fftA_fwd(float2 r[16], int t, const float2* tw,
                                         const float2* tw4, const float2* tw8) {
    #pragma unroll
    for (int j = 0; j < 8; ++j) bf_fwd(r[j], r[j + 8], tw[t + 8 * j]);
    #pragma unroll
    for (int g = 0; g < 8; ++g) { int j = ((g & ~3) << 1) | (g & 3); bf_fwd(r[j], r[j + 4], tw[2 * (t + 8 * (j & 3))]); }
    #pragma unroll
    for (int g = 0; g < 8; ++g) { int j = ((g & ~1) << 1) | (g & 1); bf_fwd(r[j], r[j + 2], tw4[t + 8 * (j & 1)]); }
    #pragma unroll
    for (int g = 0; g < 8; ++g) { int j = 2 * g; bf_fwd(r[j], r[j + 1], tw8[t]); }
}
__device__ __forceinline__ void fftA_inv(float2 r[16], int t, const float2* tw,
                                         const float2* tw4, const float2* tw8) {
    #pragma unroll
    for (int g = 0; g < 8; ++g) { int j = 2 * g; bf_inv(r[j], r[j + 1], tw8[t]); }
    #pragma unroll
    for (int g = 0; g < 8; ++g) { int j = ((g & ~1) << 1) | (g & 1); bf_inv(r[j], r[j + 2], tw4[t + 8 * (j & 1)]); }
    #pragma unroll
    for (int g = 0; g < 8; ++g) { int j = ((g & ~3) << 1) | (g & 3); bf_inv(r[j], r[j + 4], tw[2 * (t + 8 * (j & 3))]); }
    #pragma unroll
    for (int j = 0; j < 8; ++j) bf_inv(r[j], r[j + 8], tw[t + 8 * j]);
}
__device__ __forceinline__ void fftB_fwd(float2 r[16], const float2* tw) {
    #pragma unroll
    for (int g = 0; g < 8; ++g) { int m = ((g & ~3) << 1) | (g & 3); bf_fwd(r[m], r[m + 4], tw[(m & 3) << 4]); }
    #pragma unroll
    for (int g = 0; g < 8; ++g) { int m = ((g & ~1) << 1) | (g & 1); bf_fwd(r[m], r[m + 2], tw[(m & 1) << 5]); }
    #pragma unroll
    for (int g = 0; g < 8; ++g) bf_triv_fwd(r[2 * g], r[2 * g + 1]);
}
__device__ __forceinline__ void fftB_inv(float2 r[16], const float2* tw) {
    #pragma unroll
    for (int g = 0; g < 8; ++g) bf_triv_fwd(r[2 * g], r[2 * g + 1]);
    #pragma unroll
    for (int g = 0; g < 8; ++g) { int m = ((g & ~1) << 1) | (g & 1); bf_inv(r[m], r[m + 2], tw[(m & 1) << 5]); }
    #pragma unroll
    for (int g = 0; g < 8; ++g) { int m = ((g & ~3) << 1) | (g & 3); bf_inv(r[m], r[m + 4], tw[(m & 3) << 4]); }
}
__device__ __forceinline__ void init_tw1(float2* tw, int nthr) {
    for (int i = threadIdx.x; i < 64; i += nthr) {
        float sn, cs; sincospif(i * (1.0f / 64.0f), &sn, &cs);
        tw[i] = make_float2(cs, -sn);
    }
}
__device__ __forceinline__ void init_tw3(float2* tw, float2* tw4, float2* tw8, int nthr) {
    for (int i = threadIdx.x; i < 64; i += nthr) {
        float sn, cs; sincospif(i * (1.0f / 64.0f), &sn, &cs);
        float2 w = make_float2(cs, -sn);
        tw[i] = w;
        if (!(i & 3)) tw4[i >> 2] = w;
        if (!(i & 7)) tw8[i >> 3] = w;
    }
}

// Pass A: pack v1 + i*v2, forward FFT along x then y per (b,z) slab.
// 256 threads, 2 CTAs/SM; half2 tile; each thread handles 2 slots x 2 reps per phase.
__global__ __launch_bounds__(256, 2) void passA(const float* __restrict__ v1,
                                                const float* __restrict__ v2) {
    extern __shared__ char raw[];
    __half2* tile = (__half2*)raw;                     // 128*128 half2 = 65,536 B
    float2* tw = (float2*)(raw + 65536);               // 64 entries
    init_tw1(tw, 256);
    const int tid = threadIdx.x, w2 = tid >> 5, lane = tid & 31;
    const int t = lane & 7, q = (lane >> 3) & 1, h = lane >> 4;
    const size_t base = (size_t)blockIdx.x * SLAB;
    float2 r[16];
    __syncthreads();
    #pragma unroll 1
    for (int it = 0; it < 4; ++it) {                   // x-dim, pattern A' (float2 gmem in)
        const int y = 2 * w2 + 32 * (it >> 1) + 16 * q + h + 64 * (it & 1);
        const float* p1 = v1 + base + y * VDIM + 2 * t;
        const float* p2 = v2 + base + y * VDIM + 2 * t;
        #pragma unroll
        for (int j = 0; j < 8; ++j) {
            const float2 a = *(const float2*)(p1 + 16 * j);
            const float2 b = *(const float2*)(p2 + 16 * j);
            r[2 * j]     = make_float2(a.x, b.x);
            r[2 * j + 1] = make_float2(a.y, b.y);
        }
        fftA2_fwd(r, t, tw);
        #pragma unroll
        for (int k = 0; k < 16; ++k)
            tile[sidxAC(y, 16 * (k >> 1) + 2 * t + (k & 1))] = pack_h2(r[k]);
    }
    __syncwarp();
    #pragma unroll 1
    for (int it = 0; it < 4; ++it) {                   // x-dim, pattern B'
        const int y = 2 * w2 + 32 * (it >> 1) + q + 16 * h + 64 * (it & 1);
        #pragma unroll
        for (int m = 0; m < 16; ++m) r[m] = unpack_h2(tile[sidxAC(y, 16 * t + m)]);
        fftB2_fwd(r, tw);
        #pragma unroll
        for (int m = 0; m < 16; ++m) tile[sidxAC(y, 16 * t + m)] = pack_h2(r[m]);
    }
    __syncthreads();
    #pragma unroll 1
    for (int it = 0; it < 4; ++it) {                   // y-dim, pattern A'
        const int x = 2 * w2 + 32 * (it >> 1) + 16 * q + h + 64 * (it & 1);
        #pragma unroll
        for (int k = 0; k < 16; ++k)
            r[k] = unpack_h2(tile[sidxAC(16 * (k >> 1) + 2 * t + (k & 1), x)]);
        fftA2_fwd(r, t, tw);
        #pragma unroll
        for (int k = 0; k < 16; ++k)
            tile[sidxAC(16 * (k >> 1) + 2 * t + (k & 1), x)] = pack_h2(r[k]);
    }
    __syncthreads();
    #pragma unroll 1
    for (int it = 0; it < 4; ++it) {                   // y-dim, pattern B' (coalesced g_Z out)
        const int x = lane + 32 * (it >> 1) + 64 * (it & 1);
        #pragma unroll
        for (int m = 0; m < 16; ++m) r[m] = unpack_h2(tile[sidxAC(16 * w2 + m, x)]);
        fftB2_fwd(r, tw);
        #pragma unroll
        for (int m = 0; m < 16; ++m)
            g_Z[base + (size_t)(16 * w2 + m) * VDIM + x] = pack_h2(r[m]);
    }
}

__device__ __forceinline__ float2 Hval(float2 Z, float2 Zn) {
    const float px = Z.x + Zn.x, py = Z.y - Zn.y;   // 2*F1
    const float qx = Z.x - Zn.x, qy = Z.y + Zn.y;   // 2i*F2
    return make_float2(0.25f * (px * qy - py * qx),
                       0.25f * (px * qx + py * qy));
}

// Pass B: unchanged from passing R11 kernel (fp32 tile, 256 thr, 2 CTAs/SM).
__global__ __launch_bounds__(256, 2) void passB() {
    extern __shared__ char raw[];
    float2* tile = (float2*)raw;                    // 64 lines x 128 (z)
    float2* tw = tile + 64 * 128; float2* tw4 = tw + 64; float2* tw8 = tw4 + 16;
    const int xt = blockIdx.x, jy = blockIdx.y, b = blockIdx.z;
    const int jy2 = bneg7(jy);
    const int xt2 = (xt < 2) ? xt : (5 - xt);
    if (jy2 < jy || (jy2 == jy && xt2 < xt)) return;
    const bool full = (jy2 == jy);
    init_tw3(tw, tw4, tw8, 256);
    const int tid = threadIdx.x;
    const int t = (tid >> 4) & 7;
    const int l0 = ((tid >> 7) << 4) | (tid & 15);
    const int l1 = l0 + 32;
    const size_t vb = (size_t)b * VOL;
    const size_t gb0 = vb + (size_t)jy  * VDIM + (32 * xt  + l0);
    const size_t gb1 = vb + (size_t)jy2 * VDIM + (32 * xt2 + l0);
    const float SCL = 1.0f / (float)VOL;
    float2 r[16];
    __syncthreads();
    #pragma unroll
    for (int j = 0; j < 16; ++j) r[j] = unpack_h2(g_Z[gb0 + (size_t)(t + 8 * j) * SLAB]);
    fftA_fwd(r, t, tw, tw4, tw8);
    #pragma unroll
    for (int j = 0; j < 16; ++j) tile[sidxB(l0, t + 8 * j)] = r[j];
    #pragma unroll
    for (int j = 0; j < 16; ++j) r[j] = unpack_h2(g_Z[gb1 + (size_t)(t + 8 * j) * SLAB]);
    fftA_fwd(r, t, tw, tw4, tw8);
    #pragma unroll
    for (int j = 0; j < 16; ++j) tile[sidxB(l1, t + 8 * j)] = r[j];
    __syncthreads();
    #pragma unroll
    for (int m = 0; m < 16; ++m) r[m] = tile[sidxB(l0, 16 * t + m)];
    fftB_fwd(r, tw);
    #pragma unroll
    for (int m = 0; m < 16; ++m) tile[sidxB(l0, 16 * t + m)] = r[m];
    #pragma unroll
    for (int m = 0; m < 16; ++m) r[m] = tile[sidxB(l1, 16 * t + m)];
    fftB_fwd(r, tw);
    #pragma unroll
    for (int m = 0; m < 16; ++m) tile[sidxB(l1, 16 * t + m)] = r[m];
    __syncthreads();
    #pragma unroll 1
    for (int i = tid; i < 32 * 128; i += 256) {
        const int jz = i & 127, row = i >> 7;
        const int jzn = bneg7(jz);
        if (jzn < jz) continue;
        const int pr = 32 + bneg7(32 * xt + row) - 32 * xt2;
        const float2 a1 = tile[sidxB(row, jz)], a2 = tile[sidxB(row, jzn)];
        const float2 b1 = tile[sidxB(pr, jz)],  b2 = tile[sidxB(pr, jzn)];
        tile[sidxB(row, jz)]  = Hval(a1, b2);
        tile[sidxB(pr, jz)]   = Hval(b1, a2);
        tile[sidxB(row, jzn)] = Hval(a2, b1);
        tile[sidxB(pr, jzn)]  = Hval(b2, a1);
    }
    __syncthreads();
    #pragma unroll
    for (int m = 0; m < 16; ++m) r[m] = tile[sidxB(l0, 16 * t + m)];
    fftB_inv(r, tw);
    #pragma unroll
    for (int m = 0; m < 16; ++m) tile[sidxB(l0, 16 * t + m)] = r[m];
    if (full) {
        #pragma unroll
        for (int m = 0; m < 16; ++m) r[m] = tile[sidxB(l1, 16 * t + m)];
        fftB_inv(r, tw);
        #pragma unroll
        for (int m = 0; m < 16; ++m) tile[sidxB(l1, 16 * t + m)] = r[m];
    }
    __syncthreads();
    #pragma unroll
    for (int j = 0; j < 16; ++j) r[j] = tile[sidxB(l0, t + 8 * j)];
    fftA_inv(r, t, tw, tw4, tw8);
    #pragma unroll
    for (int j = 0; j < 16; ++j)
        g_Z[gb0 + (size_t)(t + 8 * j) * SLAB] =
            pack_h2(make_float2(r[j].x * SCL, r[j].y * SCL));
    if (full) {
        #pragma unroll
        for (int j = 0; j < 16; ++j) r[j] = tile[sidxB(l1, t + 8 * j)];
        fftA_inv(r, t, tw, tw4, tw8);
        #pragma unroll
        for (int j = 0; j < 16; ++j)
            g_Z[gb1 + (size_t)(t + 8 * j) * SLAB] =
                pack_h2(make_float2(r[j].x * SCL, r[j].y * SCL));
    }
}

// Pass C: gather half-spectrum + mirror conj fill (lossless, g_Z already fp16),
// inverse y then x FFTs, float2 out. 256 threads, 2 CTAs/SM, half2 tile.
__global__ __launch_bounds__(256, 2) void passC(float* __restrict__ out) {
    extern __shared__ char raw[];
    __half2* tile = (__half2*)raw;
    float2* tw = (float2*)(raw + 65536);
    init_tw1(tw, 256);
    const int tid = threadIdx.x, w2 = tid >> 5, lane = tid & 31;
    const int t = lane & 7, q = (lane >> 3) & 1, h = lane >> 4;
    const size_t base = (size_t)blockIdx.x * SLAB;
    float2 r[16];
    __syncthreads();
    // gather copy-in: load kept rows (jy <= bneg7(jy)); mirror-fill conj rows.
    #pragma unroll 1
    for (int jy = w2; jy < 128; jy += 8) {
        const int jy2 = bneg7(jy);
        if (jy > jy2) continue;
        #pragma unroll
        for (int k = 0; k < 4; ++k) {
            const int xx = lane + 32 * k;
            __half2 v = g_Z[base + (size_t)jy * VDIM + xx];
            tile[sidxAC(jy, xx)] = v;
            if (jy2 != jy) {
                __half2 c = v; c.y = __hneg(c.y);
                tile[sidxAC(jy2, bneg7(xx))] = c;
            }
        }
    }
    __syncthreads();
    #pragma unroll 1
    for (int it = 0; it < 4; ++it) {                   // y-dim, pattern B' (from smem)
        const int x = lane + 32 * (it >> 1) + 64 * (it & 1);
        #pragma unroll
        for (int m = 0; m < 16; ++m) r[m] = unpack_h2(tile[sidxAC(16 * w2 + m, x)]);
        fftB2_inv(r, tw);
        #pragma unroll
        for (int m = 0; m < 16; ++m) tile[sidxAC(16 * w2 + m, x)] = pack_h2(r[m]);
    }
    __syncthreads();
    #pragma unroll 1
    for (int it = 0; it < 4; ++it) {                   // y-dim, pattern A'
        const int x = 2 * w2 + 32 * (it >> 1) + 16 * q + h + 64 * (it & 1);
        #pragma unroll
        for (int k = 0; k < 16; ++k)
            r[k] = unpack_h2(tile[sidxAC(16 * (k >> 1) + 2 * t + (k & 1), x)]);
        fftA2_inv(r, t, tw);
        #pragma unroll
        for (int k = 0; k < 16; ++k)
            tile[sidxAC(16 * (k >> 1) + 2 * t + (k & 1), x)] = pack_h2(r[k]);
    }
    __syncthreads();
    #pragma unroll 1
    for (int it = 0; it < 4; ++it) {                   // x-dim, pattern B'
        const int y = 2 * w2 + 32 * (it >> 1) + q + 16 * h + 64 * (it & 1);
        #pragma unroll
        for (int m = 0; m < 16; ++m) r[m] = unpack_h2(tile[sidxAC(y, 16 * t + m)]);
        fftB2_inv(r, tw);
        #pragma unroll
        for (int m = 0; m < 16; ++m) tile[sidxAC(y, 16 * t + m)] = pack_h2(r[m]);
    }
    __syncwarp();
    #pragma unroll 1
    for (int it = 0; it < 4; ++it) {                   // x-dim, pattern A' -> float2 out
        const int y = 2 * w2 + 32 * (it >> 1) + 16 * q + h + 64 * (it & 1);
        #pragma unroll
        for (int k = 0; k < 16; ++k)
            r[k] = unpack_h2(tile[sidxAC(y, 16 * (k >> 1) + 2 * t + (k & 1))]);
        fftA2_inv(r, t, tw);
        float* po = out + base + y * VDIM + 2 * t;
        #pragma unroll
        for (int j = 0; j < 8; ++j)
            *(float2*)(po + 16 * j) = make_float2(r[2 * j].x, r[2 * j + 1].x);
    }
}

extern "C" void kernel_launch(void* const* d_in, const int* in_sizes, int n_in,
                              void* d_out, int out_size) {
    const float* v1 = (const float*)d_in[0];
    const float* v2 = (const float*)d_in[1];
    float* out = (float*)d_out;
    const int smAC = 65536 + 64 * (int)sizeof(float2);                 // 66,048 B
    const int smB  = (64 * 128 + 64 + 16 + 8) * (int)sizeof(float2);   // 66,240 B
    cudaFuncSetAttribute(passA, cudaFuncAttributeMaxDynamicSharedMemorySize, smAC);
    cudaFuncSetAttribute(passC, cudaFuncAttributeMaxDynamicSharedMemorySize, smAC);
    cudaFuncSetAttribute(passB, cudaFuncAttributeMaxDynamicSharedMemorySize, smB);
    passA<<<NB * VDIM, 256, smAC>>>(v1, v2);
    passB<<<dim3(4, VDIM, NB), 256, smB>>>();
    passC<<<NB * VDIM, 256, smAC>>>(out);
}